// round 8
// baseline (speedup 1.0000x reference)
#include <cuda_runtime.h>
#include <stdint.h>

#define MP1 524288
#define NXP 32768
#define PP  128
#define HT  128
#define HE  64

#define TPB   512
#define WARPS 16
#define GRID_A 148
#define STRIDE_A (GRID_A * WARPS)              // 2368
#define ITERS_A 14
#define ROW_F4 (MP1 / 4)                       // 131072
#define CPB ((ROW_F4 + GRID_A - 1) / GRID_A)   // 886

#define GRID_B 296
#define STRIDE_B (GRID_B * WARPS)              // 4736
#define ITERS_B 7

// scratch (static device arrays, no runtime alloc)
__device__ float  g_partA[PP][GRID_A];
__device__ float  g_c[PP + 1];
__device__ float4 g_jets[NXP][PP];

__device__ __forceinline__ void jet3(float z, float& T, float& s, float& d2, float& d3) {
    T  = tanhf(z);
    s  = 1.f - T * T;
    d2 = -2.f * T * s;
    d3 = -2.f * s * (1.f - 3.f * T * T);
}

// tf32 helpers (baseline PTX, compiles for sm_103)
__device__ __forceinline__ uint32_t f2tf(float f) {
    uint32_t u;
    asm("cvt.rna.tf32.f32 %0, %1;" : "=r"(u) : "f"(f));
    return u;
}
__device__ __forceinline__ void mma8(float* c, const uint32_t* a,
                                     uint32_t b0, uint32_t b1) {
    asm("mma.sync.aligned.m16n8k8.row.col.f32.tf32.tf32.f32 "
        "{%0,%1,%2,%3},{%4,%5,%6,%7},{%8,%9},{%0,%1,%2,%3};"
        : "+f"(c[0]), "+f"(c[1]), "+f"(c[2]), "+f"(c[3])
        : "r"(a[0]), "r"(a[1]), "r"(a[2]), "r"(a[3]), "r"(b0), "r"(b1));
}

// cp.async helpers (baseline sm_80 PTX)
__device__ __forceinline__ uint32_t smem_u32(const void* p) {
    uint32_t r;
    asm("{ .reg .u64 t; cvta.to.shared.u64 t, %1; cvt.u32.u64 %0, t; }" : "=r"(r) : "l"(p));
    return r;
}
__device__ __forceinline__ void cpa16(uint32_t dst, const void* src) {
    asm volatile("cp.async.cg.shared.global [%0], [%1], 16;" :: "r"(dst), "l"(src));
}
#define CPA_COMMIT() asm volatile("cp.async.commit_group;" ::: "memory")
#define CPA_WAIT1()  asm volatile("cp.async.wait_group 1;" ::: "memory")
#define CPA_WAIT0()  asm volatile("cp.async.wait_group 0;" ::: "memory")

// ================================================================= pass A
// smem float offsets
#define OFF_W0  0
#define OFF_ZC  128
#define OFF_BT2 256
#define OFF_W1  384
#define OFF_W2  (OFF_W1 + 128 * 132)           // 17280
#define OFF_H1  (OFF_W2 + 128 * 132)           // 34176
#define OFF_H2  (OFF_H1 + 128 * 72)            // 43392
#define OFF_RING (OFF_H2 + 128 * 72)           // 52608
// ring: 8 warps x 2 slots x 2 rows x 32 lanes x 4 floats = 4096 floats (16KB)
#define A_SMEM_FLOATS (OFF_RING + 4096)        // 56704 -> 226816 B
// D (epilogue staging) reuses H1 region: [n=64][m pad 132] = 8448 floats <= 9216

__global__ __launch_bounds__(TPB, 1) void k_A(
    const float* __restrict__ Wb, const float* __restrict__ a,
    const float* __restrict__ x,  const float* __restrict__ tptr,
    const float* __restrict__ Wt1, const float* __restrict__ bt1,
    const float* __restrict__ Wt2, const float* __restrict__ bt2)
{
    extern __shared__ float sm[];
    const int tid  = threadIdx.x;
    const int w    = tid >> 5;
    const int lane = tid & 31;

    // ---- stage constants + Wt2 2-way tf32 split (pad 132)
    {
        float tv = *tptr;
        if (tid < 128) {
            float w0 = Wt1[2 * tid];
            sm[OFF_W0 + tid]  = w0;
            sm[OFF_ZC + tid]  = Wt1[2 * tid + 1] * tv + bt1[tid];
            sm[OFF_BT2 + tid] = bt2[tid];
        }
#pragma unroll 4
        for (int i = tid; i < HT * HT; i += TPB) {
            int m = i >> 7, k = i & 127;
            float f  = Wt2[i];
            float hi = __uint_as_float(f2tf(f));
            float lo = __uint_as_float(f2tf(f - hi));
            sm[OFF_W1 + m * 132 + k] = hi;
            sm[OFF_W2 + m * 132 + k] = lo;
        }
    }
    __syncthreads();

    const int colbase = blockIdx.x * CPB;
    const int colend  = min(colbase + CPB, ROW_F4);
    const float4* a4  = reinterpret_cast<const float4*>(a);
    const float4* Wb4 = reinterpret_cast<const float4*>(Wb);
    float part[16];
#pragma unroll
    for (int u = 0; u < 16; ++u) part[u] = 0.f;

    const uint32_t q = lane & 3, r = lane >> 2;
    float* Dsm = sm + OFF_H1;                   // [n][132]
    const int wb = w - 8;
    // ring smem byte addresses (branch warps)
    uint32_t ring_u32 = 0;
    if (w >= 8) ring_u32 = smem_u32(sm + OFF_RING + wb * 512) + lane * 16;
    float4* ring_f4 = reinterpret_cast<float4*>(sm + OFF_RING + (w >= 8 ? wb * 512 : 0));

    for (int it = 0; it < ITERS_A; ++it) {
        const int pt0 = blockIdx.x * WARPS + it * STRIDE_A;

        // ---- phase 1: layer-1 jets, all 16 warps (1 point each) -> H1/H2
        {
            const int ptw = pt0 + w;
            const float xi = (ptw < NXP) ? x[ptw] : 0.f;
#pragma unroll
            for (int u = 0; u < 4; ++u) {
                int k = lane + 32 * u;
                float w0 = sm[OFF_W0 + k];
                float T, s, d2, d3;
                jet3(fmaf(w0, xi, sm[OFF_ZC + k]), T, s, d2, d3);
                float w2 = w0 * w0;
                float v0 = T, v1 = s * w0, v2 = d2 * w2, v3 = d3 * w2 * w0;
                float h0 = __uint_as_float(f2tf(v0));
                float h1 = __uint_as_float(f2tf(v1));
                float h2 = __uint_as_float(f2tf(v2));
                float h3 = __uint_as_float(f2tf(v3));
                *reinterpret_cast<float4*>(&sm[OFF_H1 + k * 72 + 4 * w]) =
                    make_float4(h0, h1, h2, h3);
                *reinterpret_cast<float4*>(&sm[OFF_H2 + k * 72 + 4 * w]) =
                    make_float4(__uint_as_float(f2tf(v0 - h0)),
                                __uint_as_float(f2tf(v1 - h1)),
                                __uint_as_float(f2tf(v2 - h2)),
                                __uint_as_float(f2tf(v3 - h3)));
            }
        }
        __syncthreads();   // (1) H ready; prev epilogue done

        if (w < 8) {
            // ---- MMA warps: 16 rows (m-tile w) x 64 cols, 3 split-products
            float cA[8][4], cB[8][4];
#pragma unroll
            for (int nt = 0; nt < 8; ++nt)
#pragma unroll
                for (int i = 0; i < 4; ++i) { cA[nt][i] = 0.f; cB[nt][i] = 0.f; }

            const uint32_t* W1u = reinterpret_cast<const uint32_t*>(sm + OFF_W1);
            const uint32_t* W2u = reinterpret_cast<const uint32_t*>(sm + OFF_W2);
            const uint32_t* H1u = reinterpret_cast<const uint32_t*>(sm + OFF_H1);
            const uint32_t* H2u = reinterpret_cast<const uint32_t*>(sm + OFF_H2);
            const uint32_t rA0 = (16 * w + r) * 132;
            const uint32_t rA1 = rA0 + 8 * 132;

#pragma unroll 4
            for (int kk = 0; kk < 16; ++kk) {
                const uint32_t k0 = kk * 8;
                uint32_t a1[4], a2[4];
                a1[0] = W1u[rA0 + k0 + q];     a1[1] = W1u[rA1 + k0 + q];
                a1[2] = W1u[rA0 + k0 + 4 + q]; a1[3] = W1u[rA1 + k0 + 4 + q];
                a2[0] = W2u[rA0 + k0 + q];     a2[1] = W2u[rA1 + k0 + q];
                a2[2] = W2u[rA0 + k0 + 4 + q]; a2[3] = W2u[rA1 + k0 + 4 + q];
                const uint32_t kb = (k0 + q) * 72 + r;
#pragma unroll
                for (int nt = 0; nt < 8; ++nt) {
                    uint32_t b10 = H1u[kb + 8 * nt], b11 = H1u[kb + 288 + 8 * nt];
                    uint32_t b20 = H2u[kb + 8 * nt], b21 = H2u[kb + 288 + 8 * nt];
                    mma8(cA[nt], a1, b10, b11);   // W1*H1
                    mma8(cB[nt], a2, b10, b11);   // W2*H1
                    mma8(cA[nt], a1, b20, b21);   // W1*H2
                }
            }
            __syncthreads();   // (2) all H reads done
            // store D = [n][m pad 132] into H1 region
#pragma unroll
            for (int nt = 0; nt < 8; ++nt) {
                int n = 8 * nt + 2 * q;
                int m = 16 * w + r;
                Dsm[n * 132 + m]           = cA[nt][0] + cB[nt][0];
                Dsm[(n + 1) * 132 + m]     = cA[nt][1] + cB[nt][1];
                Dsm[n * 132 + m + 8]       = cA[nt][2] + cB[nt][2];
                Dsm[(n + 1) * 132 + m + 8] = cA[nt][3] + cB[nt][3];
            }
        } else {
            // ---- branch warps: cp.async double-buffered stream of Wb rows
            // rows owned: wb + 8u, u<16. 16 sub-chunks of 2 rows (u=2sc,2sc+1)
            float4 av  = make_float4(0.f, 0.f, 0.f, 0.f);
            float4 pav = av;
            bool v = false, pv = false;
            int cq = 0;
#pragma unroll
            for (int j = 0; j < 16; ++j) {
                if ((j & 7) == 0) {
                    int cidx = colbase + (it * 2 + (j >> 3)) * 32 + lane;
                    v  = cidx < colend;
                    av = v ? __ldg(a4 + cidx) : make_float4(0.f, 0.f, 0.f, 0.f);
                    cq = cidx;
                }
                const int sc = j & 7, slot = j & 1;
                if (v) {
                    int u0 = 2 * sc;
                    cpa16(ring_u32 + slot * 1024,
                          Wb4 + (size_t)(wb + 8 * u0) * ROW_F4 + cq);
                    cpa16(ring_u32 + slot * 1024 + 512,
                          Wb4 + (size_t)(wb + 8 * (u0 + 1)) * ROW_F4 + cq);
                }
                CPA_COMMIT();
                if (j >= 1) {
                    CPA_WAIT1();
                    if (pv) {
                        const int ps = (j - 1) & 1, pu = 2 * ((j - 1) & 7);
                        float4 w0 = ring_f4[ps * 64 + lane];
                        float4 w1 = ring_f4[ps * 64 + 32 + lane];
                        part[pu]     += w0.x * pav.x + w0.y * pav.y + w0.z * pav.z + w0.w * pav.w;
                        part[pu + 1] += w1.x * pav.x + w1.y * pav.y + w1.z * pav.z + w1.w * pav.w;
                    }
                }
                pav = av; pv = v;
            }
            CPA_WAIT0();
            if (pv) {
                float4 w0 = ring_f4[1 * 64 + lane];
                float4 w1 = ring_f4[1 * 64 + 32 + lane];
                part[14] += w0.x * pav.x + w0.y * pav.y + w0.z * pav.z + w0.w * pav.w;
                part[15] += w1.x * pav.x + w1.y * pav.y + w1.z * pav.z + w1.w * pav.w;
            }
            __syncthreads();   // (2) matches MMA warps' barrier
        }
        __syncthreads();       // (3) D ready

        // ---- epilogue: tanh jets -> g_jets (all 16 warps, 1 point each)
        {
            const int pt = pt0 + w;
            if (pt < NXP) {
#pragma unroll
                for (int u = 0; u < 4; ++u) {
                    int m = lane + 32 * u;
                    float z0 = Dsm[(4 * w + 0) * 132 + m] + sm[OFF_BT2 + m];
                    float a1 = Dsm[(4 * w + 1) * 132 + m];
                    float a2 = Dsm[(4 * w + 2) * 132 + m];
                    float a3 = Dsm[(4 * w + 3) * 132 + m];
                    float T, s, d2, d3;
                    jet3(z0, T, s, d2, d3);
                    float g1 = s * a1;
                    float g2 = s * a2 + d2 * a1 * a1;
                    float g3 = s * a3 + 3.f * d2 * a1 * a2 + d3 * a1 * a1 * a1;
                    g_jets[pt][m] = make_float4(T, g1, g2, g3);
                }
            }
        }
        __syncthreads();       // (4) D reads done before next phase-1 overwrites H1
    }

    // ---- branch partials (deterministic, per-block)
    if (w >= 8) {
#pragma unroll
        for (int u = 0; u < 16; ++u) {
            int row = wb + 8 * u;
            float v = part[u];
#pragma unroll
            for (int o = 16; o; o >>= 1) v += __shfl_down_sync(0xffffffffu, v, o);
            if (lane == 0) g_partA[row][blockIdx.x] = v;
        }
    }
}

// ======================================================== coeff: b, c, d0
__global__ void k_coeff(const float* __restrict__ Wt3, const float* __restrict__ bt3,
                        const float* __restrict__ bb) {
    __shared__ float sb[PP];
    __shared__ float w4[4];
    int k = threadIdx.x;
    float b = bb[k];
#pragma unroll 4
    for (int i = 0; i < GRID_A; ++i) b += g_partA[k][i];
    sb[k] = b;
    __syncthreads();
    float s = 0.f;
#pragma unroll 8
    for (int p = 0; p < PP; ++p) s += sb[p] * Wt3[p * PP + k];
    g_c[k] = s;
    float v = sb[k] * bt3[k];
    for (int o = 16; o; o >>= 1) v += __shfl_down_sync(0xffffffffu, v, o);
    if ((k & 31) == 0) w4[k >> 5] = v;
    __syncthreads();
    if (k == 0) g_c[PP] = w4[0] + w4[1] + w4[2] + w4[3];
}

// ================================================================= pass B
#define EPAD 68
#define B_WE2 0
#define B_C   4352
#define B_P   4480
#define B_Q   4544
#define B_BE1 4608
#define B_BE2 4672
#define B_W3  4736
#define B_D0  4800
#define B_E   4804
#define B_SMEM (B_E + WARPS * 768)

__global__ __launch_bounds__(TPB, 2) void k_B(
    const float* __restrict__ We1, const float* __restrict__ be1,
    const float* __restrict__ We2, const float* __restrict__ be2,
    const float* __restrict__ We3, float* __restrict__ out)
{
    extern __shared__ float sm[];
    const int tid = threadIdx.x;

    {
        const float4* se = reinterpret_cast<const float4*>(We2);
#pragma unroll
        for (int i = tid; i < HE * HE / 4; i += TPB) {
            int e = i * 4, j = e >> 6, k = e & 63;
            *reinterpret_cast<float4*>(&sm[B_WE2 + j * EPAD + k]) = se[i];
        }
        if (tid < 128) sm[B_C + tid] = g_c[tid];
        if (tid < 64) {
            sm[B_P + tid]   = We1[2 * tid];
            sm[B_Q + tid]   = We1[2 * tid + 1];
            sm[B_BE1 + tid] = be1[tid];
            sm[B_BE2 + tid] = be2[tid];
            sm[B_W3 + tid]  = We3[tid];
        }
        if (tid == 0) sm[B_D0] = g_c[PP];
    }
    __syncthreads();

    const int w    = tid >> 5;
    const int lane = tid & 31;
    float* E1 = sm + B_E + w * 768;
    const int base_pt = blockIdx.x * WARPS + w;
    const float c0 = sm[B_C + lane], c1 = sm[B_C + lane + 32];
    const float c2 = sm[B_C + lane + 64], c3 = sm[B_C + lane + 96];
    const float d0 = sm[B_D0];

    for (int it = 0; it < ITERS_B; ++it) {
        const int pt = base_pt + it * STRIDE_B;
        const bool active = pt < NXP;

        float p0, p1, p2, p3;
        {
            float4 j0, j1, j2, j3;
            if (active) {
                j0 = g_jets[pt][lane];      j1 = g_jets[pt][lane + 32];
                j2 = g_jets[pt][lane + 64]; j3 = g_jets[pt][lane + 96];
            } else {
                j0 = j1 = j2 = j3 = make_float4(0.f, 0.f, 0.f, 0.f);
            }
            p0 = c0 * j0.x + c1 * j1.x + c2 * j2.x + c3 * j3.x;
            p1 = c0 * j0.y + c1 * j1.y + c2 * j2.y + c3 * j3.y;
            p2 = c0 * j0.z + c1 * j1.z + c2 * j2.z + c3 * j3.z;
            p3 = c0 * j0.w + c1 * j1.w + c2 * j2.w + c3 * j3.w;
        }
#pragma unroll
        for (int o = 16; o; o >>= 1) {
            p0 += __shfl_xor_sync(0xffffffffu, p0, o);
            p1 += __shfl_xor_sync(0xffffffffu, p1, o);
            p2 += __shfl_xor_sync(0xffffffffu, p2, o);
            p3 += __shfl_xor_sync(0xffffffffu, p3, o);
        }
        const float u0 = p0 + d0, u1 = p1, u2 = p2, u3 = p3;

#pragma unroll
        for (int m = 0; m < 2; ++m) {
            int e = lane + 32 * m;
            float pp = sm[B_P + e], qq = sm[B_Q + e];
            float T, s, d2, d3;
            jet3(pp * u0 + qq * u1 + sm[B_BE1 + e], T, s, d2, d3);
            float* eb = &E1[12 * e];
            *reinterpret_cast<float4*>(eb) = make_float4(T, s * pp, s * qq, d2 * pp * pp);
            *reinterpret_cast<float4*>(eb + 4) =
                make_float4(d2 * pp * qq, d2 * qq * qq, d3 * pp * pp * qq, d3 * pp * qq * qq);
            eb[8] = d3 * qq * qq * qq;
        }
        __syncwarp();

        float b[2][9];
#pragma unroll
        for (int m = 0; m < 2; ++m)
#pragma unroll
            for (int s9 = 0; s9 < 9; ++s9) b[m][s9] = 0.f;
#pragma unroll 4
        for (int k4 = 0; k4 < 16; ++k4) {
            float4 wv0 = *reinterpret_cast<const float4*>(&sm[B_WE2 + lane * EPAD + 4 * k4]);
            float4 wv1 = *reinterpret_cast<const float4*>(&sm[B_WE2 + (lane + 32) * EPAD + 4 * k4]);
#pragma unroll
            for (int i = 0; i < 4; ++i) {
                const float* e = &E1[12 * (4 * k4 + i)];
                float4 eA = *reinterpret_cast<const float4*>(e);
                float4 eB = *reinterpret_cast<const float4*>(e + 4);
                float  eC = e[8];
                float wk0 = (i == 0) ? wv0.x : (i == 1) ? wv0.y : (i == 2) ? wv0.z : wv0.w;
                float wk1 = (i == 0) ? wv1.x : (i == 1) ? wv1.y : (i == 2) ? wv1.z : wv1.w;
                b[0][0] += wk0 * eA.x; b[0][1] += wk0 * eA.y; b[0][2] += wk0 * eA.z; b[0][3] += wk0 * eA.w;
                b[0][4] += wk0 * eB.x; b[0][5] += wk0 * eB.y; b[0][6] += wk0 * eB.z; b[0][7] += wk0 * eB.w;
                b[0][8] += wk0 * eC;
                b[1][0] += wk1 * eA.x; b[1][1] += wk1 * eA.y; b[1][2] += wk1 * eA.z; b[1][3] += wk1 * eA.w;
                b[1][4] += wk1 * eB.x; b[1][5] += wk1 * eB.y; b[1][6] += wk1 * eB.z; b[1][7] += wk1 * eB.w;
                b[1][8] += wk1 * eC;
            }
        }

        float q0 = 0.f, q1 = 0.f, q2 = 0.f, q3 = 0.f, q4 = 0.f;
#pragma unroll
        for (int m = 0; m < 2; ++m) {
            int o = lane + 32 * m;
            float az0  = b[m][0] + sm[B_BE2 + o];
            float ay   = b[m][1], az   = b[m][2];
            float ayy  = b[m][3], ayz  = b[m][4], azz = b[m][5];
            float ayyz = b[m][6], ayzz = b[m][7], azzz = b[m][8];
            float T, s, d2, d3;
            jet3(az0, T, s, d2, d3);
            float vyy  = s * ayy  + d2 * ay * ay;
            float vzz  = s * azz  + d2 * az * az;
            float vyyz = s * ayyz + d2 * (ayy * az + 2.f * ayz * ay) + d3 * ay * ay * az;
            float vyzz = s * ayzz + d2 * (azz * ay + 2.f * ayz * az) + d3 * ay * az * az;
            float vzzz = s * azzz + 3.f * d2 * azz * az + d3 * az * az * az;
            float w3 = sm[B_W3 + o];
            q0 += w3 * vyy; q1 += w3 * vzz; q2 += w3 * vyyz; q3 += w3 * vyzz; q4 += w3 * vzzz;
        }
#pragma unroll
        for (int o = 16; o; o >>= 1) {
            q0 += __shfl_xor_sync(0xffffffffu, q0, o);
            q1 += __shfl_xor_sync(0xffffffffu, q1, o);
            q2 += __shfl_xor_sync(0xffffffffu, q2, o);
            q3 += __shfl_xor_sync(0xffffffffu, q3, o);
            q4 += __shfl_xor_sync(0xffffffffu, q4, o);
        }
        if (lane == 0 && active) {
            out[pt] = -q0 * u1 + q1 * u3 + q2 * u1 * u1
                    + 2.f * q3 * u1 * u2 + q4 * u2 * u2;
        }
        __syncwarp();
    }
}

// ---------------------------------------------------------------- launch
extern "C" void kernel_launch(void* const* d_in, const int* in_sizes, int n_in,
                              void* d_out, int out_size) {
    const float* a   = (const float*)d_in[0];
    const float* x   = (const float*)d_in[1];
    const float* t   = (const float*)d_in[2];
    const float* Wb  = (const float*)d_in[3];
    const float* bb  = (const float*)d_in[4];
    const float* Wt1 = (const float*)d_in[5];
    const float* bt1 = (const float*)d_in[6];
    const float* Wt2 = (const float*)d_in[7];
    const float* bt2 = (const float*)d_in[8];
    const float* Wt3 = (const float*)d_in[9];
    const float* bt3 = (const float*)d_in[10];
    const float* We1 = (const float*)d_in[11];
    const float* be1 = (const float*)d_in[12];
    const float* We2 = (const float*)d_in[13];
    const float* be2 = (const float*)d_in[14];
    const float* We3 = (const float*)d_in[15];
    (void)in_sizes; (void)n_in;
    float* out = (float*)d_out; (void)out_size;

    size_t smemA = A_SMEM_FLOATS * sizeof(float);
    cudaFuncSetAttribute(k_A, cudaFuncAttributeMaxDynamicSharedMemorySize, (int)smemA);
    k_A<<<GRID_A, TPB, smemA>>>(Wb, a, x, t, Wt1, bt1, Wt2, bt2);

    k_coeff<<<1, 128>>>(Wt3, bt3, bb);

    size_t smemB = B_SMEM * sizeof(float);
    cudaFuncSetAttribute(k_B, cudaFuncAttributeMaxDynamicSharedMemorySize, (int)smemB);
    k_B<<<GRID_B, TPB, smemB>>>(We1, be1, We2, be2, We3, out);
}

// round 9
// speedup vs baseline: 1.1675x; 1.1675x over previous
#include <cuda_runtime.h>
#include <stdint.h>

#define MP1 524288
#define NXP 32768
#define PP  128
#define HT  128
#define HE  64

#define TPB_A 1024
#define TPB   512
#define WARPS 16
#define GRID_A 148
#define STRIDE_A (GRID_A * 16)                 // 2368 (16 points per block-iter)
#define ITERS_A 14
#define ROW_F4 (MP1 / 4)                       // 131072
#define CPB ((ROW_F4 + GRID_A - 1) / GRID_A)   // 886

#define GRID_B 296
#define STRIDE_B (GRID_B * WARPS)              // 4736
#define ITERS_B 7

// scratch (static device arrays, no runtime alloc)
__device__ float  g_partA[PP][GRID_A];
__device__ float  g_c[PP + 1];
__device__ float4 g_jets[NXP][PP];

__device__ __forceinline__ void jet3(float z, float& T, float& s, float& d2, float& d3) {
    T  = tanhf(z);
    s  = 1.f - T * T;
    d2 = -2.f * T * s;
    d3 = -2.f * s * (1.f - 3.f * T * T);
}

// tf32 helpers (baseline PTX, compiles for sm_103)
__device__ __forceinline__ uint32_t f2tf(float f) {
    uint32_t u;
    asm("cvt.rna.tf32.f32 %0, %1;" : "=r"(u) : "f"(f));
    return u;
}
__device__ __forceinline__ void mma8(float* c, const uint32_t* a,
                                     uint32_t b0, uint32_t b1) {
    asm("mma.sync.aligned.m16n8k8.row.col.f32.tf32.tf32.f32 "
        "{%0,%1,%2,%3},{%4,%5,%6,%7},{%8,%9},{%0,%1,%2,%3};"
        : "+f"(c[0]), "+f"(c[1]), "+f"(c[2]), "+f"(c[3])
        : "r"(a[0]), "r"(a[1]), "r"(a[2]), "r"(a[3]), "r"(b0), "r"(b1));
}

// ================================================================= pass A
// smem float offsets
#define OFF_W0  0
#define OFF_ZC  128
#define OFF_BT2 256
#define OFF_W1  384
#define OFF_W2  (OFF_W1 + 128 * 132)           // 17280
#define OFF_H1  (OFF_W2 + 128 * 132)           // 34176
#define OFF_H2  (OFF_H1 + 128 * 72)            // 43392
#define A_SMEM_FLOATS (OFF_H2 + 128 * 72)      // 52608 -> 210432 B
// D (epilogue staging) reuses H1 region: [n=64][m pad 132] = 8448 floats <= 9216

__global__ __launch_bounds__(TPB_A, 1) void k_A(
    const float* __restrict__ Wb, const float* __restrict__ a,
    const float* __restrict__ x,  const float* __restrict__ tptr,
    const float* __restrict__ Wt1, const float* __restrict__ bt1,
    const float* __restrict__ Wt2, const float* __restrict__ bt2)
{
    extern __shared__ float sm[];
    const int tid  = threadIdx.x;
    const int w    = tid >> 5;                  // 0..31
    const int lane = tid & 31;

    // ---- stage constants + Wt2 2-way tf32 split (pad 132)
    {
        float tv = *tptr;
        if (tid < 128) {
            float w0 = Wt1[2 * tid];
            sm[OFF_W0 + tid]  = w0;
            sm[OFF_ZC + tid]  = Wt1[2 * tid + 1] * tv + bt1[tid];
            sm[OFF_BT2 + tid] = bt2[tid];
        }
#pragma unroll 4
        for (int i = tid; i < HT * HT; i += TPB_A) {
            int m = i >> 7, k = i & 127;
            float f  = Wt2[i];
            float hi = __uint_as_float(f2tf(f));
            float lo = __uint_as_float(f2tf(f - hi));
            sm[OFF_W1 + m * 132 + k] = hi;
            sm[OFF_W2 + m * 132 + k] = lo;
        }
    }
    __syncthreads();

    const int colbase = blockIdx.x * CPB;
    const int colend  = min(colbase + CPB, ROW_F4);
    const float4* a4  = reinterpret_cast<const float4*>(a);
    const float4* Wb4 = reinterpret_cast<const float4*>(Wb);
    float part[8];
#pragma unroll
    for (int u = 0; u < 8; ++u) part[u] = 0.f;

    const uint32_t q = lane & 3, r = lane >> 2;
    float* Dsm = sm + OFF_H1;                   // [n][132]
    const int p    = w & 15;                    // point index within batch
    const int half = w >> 4;                    // unit-half for phase1/epilogue
    const int mt   = w >> 1,  nh = w & 1;       // MMA warp tile coords (w<16)
    const int wb   = w - 16;                    // branch warp id (w>=16)

    for (int it = 0; it < ITERS_A; ++it) {
        const int pt0 = blockIdx.x * 16 + it * STRIDE_A;

        // ---- phase 1: layer-1 jets (2 warps per point, 2 units per lane)
        {
            const int ptw = pt0 + p;
            const float xi = (ptw < NXP) ? x[ptw] : 0.f;
#pragma unroll
            for (int u = 0; u < 2; ++u) {
                int k = 64 * half + lane + 32 * u;
                float w0 = sm[OFF_W0 + k];
                float T, s, d2, d3;
                jet3(fmaf(w0, xi, sm[OFF_ZC + k]), T, s, d2, d3);
                float w2 = w0 * w0;
                float v0 = T, v1 = s * w0, v2 = d2 * w2, v3 = d3 * w2 * w0;
                float h0 = __uint_as_float(f2tf(v0));
                float h1 = __uint_as_float(f2tf(v1));
                float h2 = __uint_as_float(f2tf(v2));
                float h3 = __uint_as_float(f2tf(v3));
                *reinterpret_cast<float4*>(&sm[OFF_H1 + k * 72 + 4 * p]) =
                    make_float4(h0, h1, h2, h3);
                *reinterpret_cast<float4*>(&sm[OFF_H2 + k * 72 + 4 * p]) =
                    make_float4(__uint_as_float(f2tf(v0 - h0)),
                                __uint_as_float(f2tf(v1 - h1)),
                                __uint_as_float(f2tf(v2 - h2)),
                                __uint_as_float(f2tf(v3 - h3)));
            }
        }
        __syncthreads();   // (1) H ready; prev epilogue done

        float c[4][4];
        if (w < 16) {
            // ---- MMA warps: m-tile mt (16 rows) x 4 n-tiles (nh half)
#pragma unroll
            for (int nt = 0; nt < 4; ++nt)
#pragma unroll
                for (int i = 0; i < 4; ++i) c[nt][i] = 0.f;

            const uint32_t* W1u = reinterpret_cast<const uint32_t*>(sm + OFF_W1);
            const uint32_t* W2u = reinterpret_cast<const uint32_t*>(sm + OFF_W2);
            const uint32_t* H1u = reinterpret_cast<const uint32_t*>(sm + OFF_H1);
            const uint32_t* H2u = reinterpret_cast<const uint32_t*>(sm + OFF_H2);
            const uint32_t rA0 = (16 * mt + r) * 132;
            const uint32_t rA1 = rA0 + 8 * 132;

#pragma unroll 4
            for (int kk = 0; kk < 16; ++kk) {
                const uint32_t k0 = kk * 8;
                uint32_t a1[4], a2[4];
                a1[0] = W1u[rA0 + k0 + q];     a1[1] = W1u[rA1 + k0 + q];
                a1[2] = W1u[rA0 + k0 + 4 + q]; a1[3] = W1u[rA1 + k0 + 4 + q];
                a2[0] = W2u[rA0 + k0 + q];     a2[1] = W2u[rA1 + k0 + q];
                a2[2] = W2u[rA0 + k0 + 4 + q]; a2[3] = W2u[rA1 + k0 + 4 + q];
                const uint32_t kb = (k0 + q) * 72 + r;
#pragma unroll
                for (int nt = 0; nt < 4; ++nt) {
                    const int ntg = 4 * nh + nt;
                    uint32_t b10 = H1u[kb + 8 * ntg], b11 = H1u[kb + 288 + 8 * ntg];
                    uint32_t b20 = H2u[kb + 8 * ntg], b21 = H2u[kb + 288 + 8 * ntg];
                    mma8(c[nt], a1, b10, b11);   // W1*H1
                    mma8(c[nt], a2, b10, b11);   // W2*H1
                    mma8(c[nt], a1, b20, b21);   // W1*H2
                }
            }
        } else {
            // ---- branch warps (16): DRAM stream, rows wb + 16u, u<8
#pragma unroll
            for (int j = 0; j < 2; ++j) {
                int cidx = colbase + (it * 2 + j) * 32 + lane;
                if (cidx < colend) {
                    float4 av = __ldg(a4 + cidx);
#pragma unroll
                    for (int u = 0; u < 8; ++u) {
                        int row = wb + 16 * u;
                        float4 wv = __ldcs(Wb4 + (size_t)row * ROW_F4 + cidx);
                        part[u] += wv.x * av.x + wv.y * av.y + wv.z * av.z + wv.w * av.w;
                    }
                }
            }
        }
        __syncthreads();   // (2) all H reads done

        if (w < 16) {      // store D = [n][m pad 132] into H1 region
#pragma unroll
            for (int nt = 0; nt < 4; ++nt) {
                const int ntg = 4 * nh + nt;
                int n = 8 * ntg + 2 * q;
                int m = 16 * mt + r;
                Dsm[n * 132 + m]           = c[nt][0];
                Dsm[(n + 1) * 132 + m]     = c[nt][1];
                Dsm[n * 132 + m + 8]       = c[nt][2];
                Dsm[(n + 1) * 132 + m + 8] = c[nt][3];
            }
        }
        __syncthreads();   // (3) D ready

        // ---- epilogue: tanh jets -> g_jets (2 warps per point)
        {
            const int pt = pt0 + p;
            if (pt < NXP) {
#pragma unroll
                for (int u = 0; u < 2; ++u) {
                    int m = 64 * half + lane + 32 * u;
                    float z0 = Dsm[(4 * p + 0) * 132 + m] + sm[OFF_BT2 + m];
                    float a1 = Dsm[(4 * p + 1) * 132 + m];
                    float a2 = Dsm[(4 * p + 2) * 132 + m];
                    float a3 = Dsm[(4 * p + 3) * 132 + m];
                    float T, s, d2, d3;
                    jet3(z0, T, s, d2, d3);
                    float g1 = s * a1;
                    float g2 = s * a2 + d2 * a1 * a1;
                    float g3 = s * a3 + 3.f * d2 * a1 * a2 + d3 * a1 * a1 * a1;
                    g_jets[pt][m] = make_float4(T, g1, g2, g3);
                }
            }
        }
        __syncthreads();   // (4) D reads done before next phase-1 overwrites H1
    }

    // ---- branch partials (deterministic, per-block)
    if (w >= 16) {
#pragma unroll
        for (int u = 0; u < 8; ++u) {
            int row = wb + 16 * u;
            float v = part[u];
#pragma unroll
            for (int o = 16; o; o >>= 1) v += __shfl_down_sync(0xffffffffu, v, o);
            if (lane == 0) g_partA[row][blockIdx.x] = v;
        }
    }
}

// ======================================================== coeff: b, c, d0
__global__ void k_coeff(const float* __restrict__ Wt3, const float* __restrict__ bt3,
                        const float* __restrict__ bb) {
    __shared__ float sb[PP];
    __shared__ float w4[4];
    int k = threadIdx.x;
    float b = bb[k];
#pragma unroll 4
    for (int i = 0; i < GRID_A; ++i) b += g_partA[k][i];
    sb[k] = b;
    __syncthreads();
    float s = 0.f;
#pragma unroll 8
    for (int p = 0; p < PP; ++p) s += sb[p] * Wt3[p * PP + k];
    g_c[k] = s;
    float v = sb[k] * bt3[k];
    for (int o = 16; o; o >>= 1) v += __shfl_down_sync(0xffffffffu, v, o);
    if ((k & 31) == 0) w4[k >> 5] = v;
    __syncthreads();
    if (k == 0) g_c[PP] = w4[0] + w4[1] + w4[2] + w4[3];
}

// ================================================================= pass B
#define EPAD 68
#define B_WE2 0
#define B_C   4352
#define B_P   4480
#define B_Q   4544
#define B_BE1 4608
#define B_BE2 4672
#define B_W3  4736
#define B_D0  4800
#define B_E   4804
#define B_SMEM (B_E + WARPS * 768)

__global__ __launch_bounds__(TPB, 2) void k_B(
    const float* __restrict__ We1, const float* __restrict__ be1,
    const float* __restrict__ We2, const float* __restrict__ be2,
    const float* __restrict__ We3, float* __restrict__ out)
{
    extern __shared__ float sm[];
    const int tid = threadIdx.x;

    {
        const float4* se = reinterpret_cast<const float4*>(We2);
#pragma unroll
        for (int i = tid; i < HE * HE / 4; i += TPB) {
            int e = i * 4, j = e >> 6, k = e & 63;
            *reinterpret_cast<float4*>(&sm[B_WE2 + j * EPAD + k]) = se[i];
        }
        if (tid < 128) sm[B_C + tid] = g_c[tid];
        if (tid < 64) {
            sm[B_P + tid]   = We1[2 * tid];
            sm[B_Q + tid]   = We1[2 * tid + 1];
            sm[B_BE1 + tid] = be1[tid];
            sm[B_BE2 + tid] = be2[tid];
            sm[B_W3 + tid]  = We3[tid];
        }
        if (tid == 0) sm[B_D0] = g_c[PP];
    }
    __syncthreads();

    const int w    = tid >> 5;
    const int lane = tid & 31;
    float* E1 = sm + B_E + w * 768;
    const int base_pt = blockIdx.x * WARPS + w;
    const float c0 = sm[B_C + lane], c1 = sm[B_C + lane + 32];
    const float c2 = sm[B_C + lane + 64], c3 = sm[B_C + lane + 96];
    const float d0 = sm[B_D0];

    for (int it = 0; it < ITERS_B; ++it) {
        const int pt = base_pt + it * STRIDE_B;
        const bool active = pt < NXP;

        float p0, p1, p2, p3;
        {
            float4 j0, j1, j2, j3;
            if (active) {
                j0 = g_jets[pt][lane];      j1 = g_jets[pt][lane + 32];
                j2 = g_jets[pt][lane + 64]; j3 = g_jets[pt][lane + 96];
            } else {
                j0 = j1 = j2 = j3 = make_float4(0.f, 0.f, 0.f, 0.f);
            }
            p0 = c0 * j0.x + c1 * j1.x + c2 * j2.x + c3 * j3.x;
            p1 = c0 * j0.y + c1 * j1.y + c2 * j2.y + c3 * j3.y;
            p2 = c0 * j0.z + c1 * j1.z + c2 * j2.z + c3 * j3.z;
            p3 = c0 * j0.w + c1 * j1.w + c2 * j2.w + c3 * j3.w;
        }
#pragma unroll
        for (int o = 16; o; o >>= 1) {
            p0 += __shfl_xor_sync(0xffffffffu, p0, o);
            p1 += __shfl_xor_sync(0xffffffffu, p1, o);
            p2 += __shfl_xor_sync(0xffffffffu, p2, o);
            p3 += __shfl_xor_sync(0xffffffffu, p3, o);
        }
        const float u0 = p0 + d0, u1 = p1, u2 = p2, u3 = p3;

#pragma unroll
        for (int m = 0; m < 2; ++m) {
            int e = lane + 32 * m;
            float pp = sm[B_P + e], qq = sm[B_Q + e];
            float T, s, d2, d3;
            jet3(pp * u0 + qq * u1 + sm[B_BE1 + e], T, s, d2, d3);
            float* eb = &E1[12 * e];
            *reinterpret_cast<float4*>(eb) = make_float4(T, s * pp, s * qq, d2 * pp * pp);
            *reinterpret_cast<float4*>(eb + 4) =
                make_float4(d2 * pp * qq, d2 * qq * qq, d3 * pp * pp * qq, d3 * pp * qq * qq);
            eb[8] = d3 * qq * qq * qq;
        }
        __syncwarp();

        float b[2][9];
#pragma unroll
        for (int m = 0; m < 2; ++m)
#pragma unroll
            for (int s9 = 0; s9 < 9; ++s9) b[m][s9] = 0.f;
#pragma unroll 4
        for (int k4 = 0; k4 < 16; ++k4) {
            float4 wv0 = *reinterpret_cast<const float4*>(&sm[B_WE2 + lane * EPAD + 4 * k4]);
            float4 wv1 = *reinterpret_cast<const float4*>(&sm[B_WE2 + (lane + 32) * EPAD + 4 * k4]);
#pragma unroll
            for (int i = 0; i < 4; ++i) {
                const float* e = &E1[12 * (4 * k4 + i)];
                float4 eA = *reinterpret_cast<const float4*>(e);
                float4 eB = *reinterpret_cast<const float4*>(e + 4);
                float  eC = e[8];
                float wk0 = (i == 0) ? wv0.x : (i == 1) ? wv0.y : (i == 2) ? wv0.z : wv0.w;
                float wk1 = (i == 0) ? wv1.x : (i == 1) ? wv1.y : (i == 2) ? wv1.z : wv1.w;
                b[0][0] += wk0 * eA.x; b[0][1] += wk0 * eA.y; b[0][2] += wk0 * eA.z; b[0][3] += wk0 * eA.w;
                b[0][4] += wk0 * eB.x; b[0][5] += wk0 * eB.y; b[0][6] += wk0 * eB.z; b[0][7] += wk0 * eB.w;
                b[0][8] += wk0 * eC;
                b[1][0] += wk1 * eA.x; b[1][1] += wk1 * eA.y; b[1][2] += wk1 * eA.z; b[1][3] += wk1 * eA.w;
                b[1][4] += wk1 * eB.x; b[1][5] += wk1 * eB.y; b[1][6] += wk1 * eB.z; b[1][7] += wk1 * eB.w;
                b[1][8] += wk1 * eC;
            }
        }

        float q0 = 0.f, q1 = 0.f, q2 = 0.f, q3 = 0.f, q4 = 0.f;
#pragma unroll
        for (int m = 0; m < 2; ++m) {
            int o = lane + 32 * m;
            float az0  = b[m][0] + sm[B_BE2 + o];
            float ay   = b[m][1], az   = b[m][2];
            float ayy  = b[m][3], ayz  = b[m][4], azz = b[m][5];
            float ayyz = b[m][6], ayzz = b[m][7], azzz = b[m][8];
            float T, s, d2, d3;
            jet3(az0, T, s, d2, d3);
            float vyy  = s * ayy  + d2 * ay * ay;
            float vzz  = s * azz  + d2 * az * az;
            float vyyz = s * ayyz + d2 * (ayy * az + 2.f * ayz * ay) + d3 * ay * ay * az;
            float vyzz = s * ayzz + d2 * (azz * ay + 2.f * ayz * az) + d3 * ay * az * az;
            float vzzz = s * azzz + 3.f * d2 * azz * az + d3 * az * az * az;
            float w3 = sm[B_W3 + o];
            q0 += w3 * vyy; q1 += w3 * vzz; q2 += w3 * vyyz; q3 += w3 * vyzz; q4 += w3 * vzzz;
        }
#pragma unroll
        for (int o = 16; o; o >>= 1) {
            q0 += __shfl_xor_sync(0xffffffffu, q0, o);
            q1 += __shfl_xor_sync(0xffffffffu, q1, o);
            q2 += __shfl_xor_sync(0xffffffffu, q2, o);
            q3 += __shfl_xor_sync(0xffffffffu, q3, o);
            q4 += __shfl_xor_sync(0xffffffffu, q4, o);
        }
        if (lane == 0 && active) {
            out[pt] = -q0 * u1 + q1 * u3 + q2 * u1 * u1
                    + 2.f * q3 * u1 * u2 + q4 * u2 * u2;
        }
        __syncwarp();
    }
}

// ---------------------------------------------------------------- launch
extern "C" void kernel_launch(void* const* d_in, const int* in_sizes, int n_in,
                              void* d_out, int out_size) {
    const float* a   = (const float*)d_in[0];
    const float* x   = (const float*)d_in[1];
    const float* t   = (const float*)d_in[2];
    const float* Wb  = (const float*)d_in[3];
    const float* bb  = (const float*)d_in[4];
    const float* Wt1 = (const float*)d_in[5];
    const float* bt1 = (const float*)d_in[6];
    const float* Wt2 = (const float*)d_in[7];
    const float* bt2 = (const float*)d_in[8];
    const float* Wt3 = (const float*)d_in[9];
    const float* bt3 = (const float*)d_in[10];
    const float* We1 = (const float*)d_in[11];
    const float* be1 = (const float*)d_in[12];
    const float* We2 = (const float*)d_in[13];
    const float* be2 = (const float*)d_in[14];
    const float* We3 = (const float*)d_in[15];
    (void)in_sizes; (void)n_in;
    float* out = (float*)d_out; (void)out_size;

    size_t smemA = A_SMEM_FLOATS * sizeof(float);
    cudaFuncSetAttribute(k_A, cudaFuncAttributeMaxDynamicSharedMemorySize, (int)smemA);
    k_A<<<GRID_A, TPB_A, smemA>>>(Wb, a, x, t, Wt1, bt1, Wt2, bt2);

    k_coeff<<<1, 128>>>(Wt3, bt3, bb);

    size_t smemB = B_SMEM * sizeof(float);
    cudaFuncSetAttribute(k_B, cudaFuncAttributeMaxDynamicSharedMemorySize, (int)smemB);
    k_B<<<GRID_B, TPB, smemB>>>(We1, be1, We2, be2, We3, out);
}